// round 5
// baseline (speedup 1.0000x reference)
#include <cuda_runtime.h>
#include <math.h>

#define N_NODES 1048576
#define N_EDGES 4194304
#define EPSV 1e-5f
#define STATS_LEN (7*24 + 3*12)
#define IDXBUF 3072

// ---------------- scratch (static device globals; no allocation) ----------------
__device__ float g_hA[N_NODES * 12];
__device__ float g_hB[N_NODES * 12];
__device__ int   g_deg[N_NODES];
__device__ int   g_off[N_NODES + 1];
__device__ int   g_cur[N_NODES];
__device__ int   g_bsum[1024];
__device__ int   g_srt[N_EDGES];      // src ids sorted by dst (CSR adjacency)
__device__ float g_stats[STATS_LEN];

__device__ __forceinline__ float* bufptr(int s) { return s == 0 ? g_hA : g_hB; }

__device__ __forceinline__ void warpsum(float& v) {
#pragma unroll
    for (int o = 16; o; o >>= 1) v += __shfl_xor_sync(0xffffffffu, v, o);
}

__device__ __forceinline__ void gath12(float* acc, const float* h, int s) {
    const float4* hp = reinterpret_cast<const float4*>(h + (size_t)s * 12);
    float4 v0 = __ldg(hp + 0), v1 = __ldg(hp + 1), v2 = __ldg(hp + 2);
    acc[0] += v0.x; acc[1] += v0.y; acc[2]  += v0.z; acc[3]  += v0.w;
    acc[4] += v1.x; acc[5] += v1.y; acc[6]  += v1.z; acc[7]  += v1.w;
    acc[8] += v2.x; acc[9] += v2.y; acc[10] += v2.z; acc[11] += v2.w;
}

// ---------------- CSR construction ----------------

__global__ void k_initz() {
    int i = blockIdx.x * blockDim.x + threadIdx.x;
    int stride = gridDim.x * blockDim.x;
    for (int j = i; j < N_NODES; j += stride) g_deg[j] = 0;
    if (i < STATS_LEN) g_stats[i] = 0.f;
}

__global__ void k_deg(const int* __restrict__ ei) {
    int e = blockIdx.x * blockDim.x + threadIdx.x;
    if (e >= N_EDGES) return;
    atomicAdd(&g_deg[ei[N_EDGES + e]], 1);
}

// block-local exclusive scan: 1024 blocks x 1024 elements (256 thr x 4)
__global__ void k_scan1() {
    __shared__ int sh[256];
    int t = threadIdx.x;
    int base = blockIdx.x * 1024 + t * 4;
    int4 d = *reinterpret_cast<int4*>(&g_deg[base]);
    int s1 = d.x + d.y, s2 = s1 + d.z, tot = s2 + d.w;
    sh[t] = tot;
    __syncthreads();
#pragma unroll
    for (int o = 1; o < 256; o <<= 1) {
        int v = (t >= o) ? sh[t - o] : 0;
        __syncthreads();
        sh[t] += v;
        __syncthreads();
    }
    int excl = sh[t] - tot;
    g_off[base + 0] = excl;
    g_off[base + 1] = excl + d.x;
    g_off[base + 2] = excl + s1;
    g_off[base + 3] = excl + s2;
    if (t == 255) g_bsum[blockIdx.x] = sh[255];
}

__global__ void k_scan2() {
    __shared__ int sh[1024];
    int t = threadIdx.x;
    int orig = g_bsum[t];
    sh[t] = orig;
    __syncthreads();
#pragma unroll
    for (int o = 1; o < 1024; o <<= 1) {
        int v = (t >= o) ? sh[t - o] : 0;
        __syncthreads();
        sh[t] += v;
        __syncthreads();
    }
    g_bsum[t] = sh[t] - orig;   // exclusive
}

__global__ void k_scan3() {
    int i = blockIdx.x * blockDim.x + threadIdx.x;
    int v = g_off[i] + g_bsum[i >> 10];
    g_off[i] = v;
    g_cur[i] = v;
    if (i == 0) g_off[N_NODES] = N_EDGES;
}

__global__ void k_place(const int* __restrict__ ei) {
    int e = blockIdx.x * blockDim.x + threadIdx.x;
    if (e >= N_EDGES) return;
    int s = ei[e];
    int d = ei[N_EDGES + e];
    int p = atomicAdd(&g_cur[d], 1);
    g_srt[p] = s;
}

// ---------------- layer 1 (3-channel gather, staged indices) ----------------
__global__ void k_node1f(const float* __restrict__ x,
                         const float* __restrict__ Wl1, const float* __restrict__ Wr1,
                         const float* __restrict__ b1) {
    __shared__ float sWl[36], sWr[36], sb[12], sSum[24];
    __shared__ int sOff[257];
    __shared__ int sIdx[IDXBUF];
    int t = threadIdx.x;
    if (t < 36) { sWl[t] = Wl1[t]; sWr[t] = Wr1[t]; }
    if (t < 12) sb[t] = b1[t];
    if (t < 24) sSum[t] = 0.f;
    int base = blockIdx.x * 256;
    sOff[t] = g_off[base + t];
    if (t == 255) sOff[256] = g_off[base + 256];
    __syncthreads();
    int rbeg = sOff[0];
    int cnt = sOff[256] - rbeg;
    bool useSh = cnt <= IDXBUF;
    if (useSh) {
        for (int j = t; j < cnt; j += 256) sIdx[j] = g_srt[rbeg + j];
    }
    __syncthreads();
    int i = base + t;
    int beg = sOff[t] - rbeg, end = sOff[t + 1] - rbeg;
    float a0 = 0.f, a1 = 0.f, a2 = 0.f;
    for (int p = beg; p < end; p++) {
        int s0 = useSh ? sIdx[p] : __ldg(&g_srt[rbeg + p]);
        a0 += __ldg(x + 3 * s0); a1 += __ldg(x + 3 * s0 + 1); a2 += __ldg(x + 3 * s0 + 2);
    }
    int dg = end - beg;
    float inv = dg > 0 ? 1.f / (float)dg : 0.f;
    float m0 = a0 * inv, m1 = a1 * inv, m2 = a2 * inv;
    float x0 = x[3 * i], x1 = x[3 * i + 1], x2 = x[3 * i + 2];
    float out[12];
#pragma unroll
    for (int k = 0; k < 12; k++) {
        float v = sb[k] + m0 * sWl[3 * k] + m1 * sWl[3 * k + 1] + m2 * sWl[3 * k + 2]
                        + x0 * sWr[3 * k] + x1 * sWr[3 * k + 1] + x2 * sWr[3 * k + 2];
        out[k] = fmaxf(v, 0.f);
    }
    float4* hp = reinterpret_cast<float4*>(g_hA + (size_t)i * 12);
    hp[0] = make_float4(out[0], out[1], out[2], out[3]);
    hp[1] = make_float4(out[4], out[5], out[6], out[7]);
    hp[2] = make_float4(out[8], out[9], out[10], out[11]);
#pragma unroll
    for (int k = 0; k < 12; k++) {
        float s = out[k], q = out[k] * out[k];
        warpsum(s); warpsum(q);
        if ((t & 31) == 0) { atomicAdd(&sSum[k], s); atomicAdd(&sSum[12 + k], q); }
    }
    __syncthreads();
    if (t < 24) atomicAdd(&g_stats[t], sSum[t]);
}

// ---------------- layers 2..8: thread-per-node, staged indices ----------------
// Block stages its contiguous g_srt range in shared (coalesced), so each thread
// issues all its gather LDG.128s back-to-back (high MLP, one latency epoch).
// BN folded to per-channel affine, gated for deg==0.
// MODE 0: conv stats of out; MODE 1 (conv8): head z1 stats.
template <int MODE>
__global__ void k_nodef(int in_sel, int out_sel,
                        const float* __restrict__ Wl, const float* __restrict__ Wr,
                        const float* __restrict__ bias,
                        const float* __restrict__ bng, const float* __restrict__ bnb,
                        int sin_off, int sout_off,
                        const float* __restrict__ linW, const float* __restrict__ linb) {
    const float* h_in = bufptr(in_sel);
    float* h_out = bufptr(out_sel);
    __shared__ float sWl[144], sWr[144], sb[12], sa[12], sc[12], sSum[24], sLW[36], sLB[6];
    __shared__ int sOff[257];
    __shared__ int sIdx[IDXBUF];
    int t = threadIdx.x;
    if (t < 144) { sWl[t] = Wl[t]; sWr[t] = Wr[t]; }
    if (t < 12) {
        sb[t] = bias[t];
        float mean = g_stats[sin_off + t] * (1.f / N_NODES);
        float var  = g_stats[sin_off + 12 + t] * (1.f / N_NODES) - mean * mean;
        float a = bng[t] * rsqrtf(var + EPSV);
        sa[t] = a;
        sc[t] = bnb[t] - mean * a;
    }
    if (t < 24) sSum[t] = 0.f;
    if (MODE == 1) {
        if (t < 36) sLW[t] = linW[t];
        if (t < 6)  sLB[t] = linb[t];
    }
    int base = blockIdx.x * 256;
    sOff[t] = g_off[base + t];
    if (t == 255) sOff[256] = g_off[base + 256];
    __syncthreads();
    int rbeg = sOff[0];
    int cnt = sOff[256] - rbeg;
    bool useSh = cnt <= IDXBUF;
    if (useSh) {
        for (int j = t; j < cnt; j += 256) sIdx[j] = g_srt[rbeg + j];
    }
    __syncthreads();

    int i = base + t;
    int beg = sOff[t] - rbeg, end = sOff[t + 1] - rbeg;
    float acc[12];
#pragma unroll
    for (int j = 0; j < 12; j++) acc[j] = 0.f;

    if (useSh) {
        int p = beg;
        for (; p + 4 <= end; p += 4) {
            int s0 = sIdx[p], s1 = sIdx[p + 1], s2 = sIdx[p + 2], s3 = sIdx[p + 3];
            gath12(acc, h_in, s0);
            gath12(acc, h_in, s1);
            gath12(acc, h_in, s2);
            gath12(acc, h_in, s3);
        }
        for (; p < end; p++) gath12(acc, h_in, sIdx[p]);
    } else {
        for (int p = beg; p < end; p++) gath12(acc, h_in, __ldg(&g_srt[rbeg + p]));
    }

    const float4* hp = reinterpret_cast<const float4*>(h_in + (size_t)i * 12);
    float4 h0 = hp[0], h1 = hp[1], h2 = hp[2];
    float hv[12] = {h0.x, h0.y, h0.z, h0.w, h1.x, h1.y, h1.z, h1.w, h2.x, h2.y, h2.z, h2.w};
    int dg = end - beg;
    float gate = dg > 0 ? 1.f : 0.f;
    float inv  = dg > 0 ? 1.f / (float)dg : 0.f;
    float m[12], hb[12];
#pragma unroll
    for (int j = 0; j < 12; j++) {
        m[j]  = acc[j] * inv * sa[j] + sc[j] * gate;   // bn(mean) fold; isolated -> 0
        hb[j] = hv[j] * sa[j] + sc[j];
    }
    float out[12];
#pragma unroll
    for (int k = 0; k < 12; k++) {
        float v = sb[k];
#pragma unroll
        for (int j = 0; j < 12; j++) v += m[j] * sWl[12 * k + j] + hb[j] * sWr[12 * k + j];
        out[k] = fmaxf(v, 0.f);
    }
    float4* op = reinterpret_cast<float4*>(h_out + (size_t)i * 12);
    op[0] = make_float4(out[0], out[1], out[2], out[3]);
    op[1] = make_float4(out[4], out[5], out[6], out[7]);
    op[2] = make_float4(out[8], out[9], out[10], out[11]);
    if (MODE == 0) {
#pragma unroll
        for (int k = 0; k < 12; k++) {
            float s = out[k], q = out[k] * out[k];
            warpsum(s); warpsum(q);
            if ((t & 31) == 0) { atomicAdd(&sSum[k], s); atomicAdd(&sSum[12 + k], q); }
        }
        __syncthreads();
        if (t < 24) atomicAdd(&g_stats[sout_off + t], sSum[t]);
    } else {
#pragma unroll
        for (int k = 0; k < 6; k++) {
            float za = sLB[k], zb = sLB[k];
#pragma unroll
            for (int j = 0; j < 6; j++) { za += out[j] * sLW[6 * k + j]; zb += out[6 + j] * sLW[6 * k + j]; }
            float s = za + zb, q = za * za + zb * zb;
            warpsum(s); warpsum(q);
            if ((t & 31) == 0) { atomicAdd(&sSum[k], s); atomicAdd(&sSum[6 + k], q); }
        }
        __syncthreads();
        if (t < 12) atomicAdd(&g_stats[sout_off + t], sSum[t]);
    }
}

// ---------------- head ----------------
template <int PASS>
__global__ void k_head(int in_sel, int out_sel,
                       const float* __restrict__ linW, const float* __restrict__ linb,
                       const float* __restrict__ g6, const float* __restrict__ b6,
                       int sin_off, int sout_off,
                       const float* __restrict__ oW, const float* __restrict__ ob,
                       float* __restrict__ outp) {
    const float* h_in = bufptr(in_sel);
    float* h_out = bufptr(out_sel);
    __shared__ float sLW[36], sLB[6], sa[6], sc[6], sSum[12], sOW[7];
    int t = threadIdx.x;
    if (t < 36) sLW[t] = linW[t];
    if (t < 6) {
        sLB[t] = linb[t];
        const float invM = 1.f / (2.f * N_NODES);
        float mean = g_stats[sin_off + t] * invM;
        float var  = g_stats[sin_off + 6 + t] * invM - mean * mean;
        float a = g6[t] * rsqrtf(var + EPSV);
        sa[t] = a;
        sc[t] = b6[t] - mean * a;
    }
    if (t < 12) sSum[t] = 0.f;
    if (PASS == 3) { if (t < 6) sOW[t] = oW[t]; if (t == 6) sOW[6] = ob[0]; }
    __syncthreads();
    int i = blockIdx.x * blockDim.x + t;
    const float4* hp = reinterpret_cast<const float4*>(h_in + (size_t)i * 12);
    float4 h0 = hp[0], h1 = hp[1], h2 = hp[2];
    float hv[12] = {h0.x, h0.y, h0.z, h0.w, h1.x, h1.y, h1.z, h1.w, h2.x, h2.y, h2.z, h2.w};
    float r[12];
#pragma unroll
    for (int half = 0; half < 2; half++) {
#pragma unroll
        for (int k = 0; k < 6; k++) {
            float z = sLB[k];
#pragma unroll
            for (int j = 0; j < 6; j++) z += hv[6 * half + j] * sLW[6 * k + j];
            r[6 * half + k] = fmaxf(z * sa[k] + sc[k], 0.f);
        }
    }
    if (PASS < 3) {
        float4* op = reinterpret_cast<float4*>(h_out + (size_t)i * 12);
        op[0] = make_float4(r[0], r[1], r[2], r[3]);
        op[1] = make_float4(r[4], r[5], r[6], r[7]);
        op[2] = make_float4(r[8], r[9], r[10], r[11]);
#pragma unroll
        for (int k = 0; k < 6; k++) {
            float za = sLB[k], zb = sLB[k];
#pragma unroll
            for (int j = 0; j < 6; j++) { za += r[j] * sLW[6 * k + j]; zb += r[6 + j] * sLW[6 * k + j]; }
            float s = za + zb, q = za * za + zb * zb;
            warpsum(s); warpsum(q);
            if ((t & 31) == 0) { atomicAdd(&sSum[k], s); atomicAdd(&sSum[6 + k], q); }
        }
        __syncthreads();
        if (t < 12) atomicAdd(&g_stats[sout_off + t], sSum[t]);
    } else {
        float oa = sOW[6], obv = sOW[6];
#pragma unroll
        for (int j = 0; j < 6; j++) { oa += r[j] * sOW[j]; obv += r[6 + j] * sOW[j]; }
        outp[2 * i]     = 1.f / (1.f + expf(-oa));
        outp[2 * i + 1] = 1.f / (1.f + expf(-obv));
    }
}

// ---------------- launch ----------------
extern "C" void kernel_launch(void* const* d_in, const int* in_sizes, int n_in,
                              void* d_out, int out_size) {
    const float* x    = (const float*)d_in[0];
    const int*   ei   = (const int*)d_in[1];
    const float* Wl1  = (const float*)d_in[2];
    const float* Wr1  = (const float*)d_in[3];
    const float* b1   = (const float*)d_in[4];
    const float* Wl   = (const float*)d_in[5];
    const float* Wr   = (const float*)d_in[6];
    const float* bb   = (const float*)d_in[7];
    const float* bng  = (const float*)d_in[8];
    const float* bnb  = (const float*)d_in[9];
    const float* linW = (const float*)d_in[10];
    const float* linb = (const float*)d_in[11];
    const float* g6   = (const float*)d_in[12];
    const float* b6   = (const float*)d_in[13];
    const float* oW   = (const float*)d_in[14];
    const float* ob   = (const float*)d_in[15];
    float* outp = (float*)d_out;

    const int EB = N_EDGES / 256;   // 16384
    const int NB = N_NODES / 256;   // 4096

    // CSR build
    k_initz<<<1024, 256>>>();
    k_deg<<<EB, 256>>>(ei);
    k_scan1<<<1024, 256>>>();
    k_scan2<<<1, 1024>>>();
    k_scan3<<<NB, 256>>>();
    k_place<<<EB, 256>>>(ei);

    // conv1 -> hA, stats slot 0
    k_node1f<<<NB, 256>>>(x, Wl1, Wr1, b1);

    int in_sel = 0, out_sel = 1;
    for (int i = 0; i < 7; i++) {
        int sin_off = 24 * i;
        if (i < 6) {
            k_nodef<0><<<NB, 256>>>(in_sel, out_sel, Wl + 144 * i, Wr + 144 * i, bb + 12 * i,
                                    bng + 12 * i, bnb + 12 * i, sin_off, 24 * (i + 1),
                                    linW, linb);
        } else {
            k_nodef<1><<<NB, 256>>>(in_sel, out_sel, Wl + 144 * i, Wr + 144 * i, bb + 12 * i,
                                    bng + 12 * i, bnb + 12 * i, sin_off, 7 * 24,
                                    linW, linb);
        }
        int tmp = in_sel; in_sel = out_sel; out_sel = tmp;
    }
    // conv8 output in hB (in_sel==1). Head: hB -> hA -> hB -> out.
    k_head<1><<<NB, 256>>>(1, 0, linW, linb, g6, b6, 168, 180, oW, ob, outp);
    k_head<2><<<NB, 256>>>(0, 1, linW, linb, g6, b6, 180, 192, oW, ob, outp);
    k_head<3><<<NB, 256>>>(1, 0, linW, linb, g6, b6, 192, 0, oW, ob, outp);
}

// round 6
// speedup vs baseline: 1.7144x; 1.7144x over previous
#include <cuda_runtime.h>
#include <cuda_fp16.h>
#include <math.h>

#define N_NODES 1048576
#define N_EDGES 4194304
#define EPSV 1e-5f
#define STATS_LEN (7*24 + 3*12)

// ---------------- scratch (static device globals; zero-init at load) ----------------
__device__ float  g_hA[N_NODES * 12];
__device__ float  g_hB[N_NODES * 12];
__device__ __half g_hHA[N_NODES * 16];   // fp16 mirror (32B rows) for gather
__device__ __half g_hHB[N_NODES * 16];
__device__ float4 g_xp[N_NODES];         // x packed to float4
__device__ int    g_deg[N_NODES];        // zero-init; tail kernel re-zeroes
__device__ int    g_off[N_NODES + 1];
__device__ int    g_cur[N_NODES];
__device__ int    g_bsum[1024];
__device__ int    g_srt[N_EDGES];        // src ids grouped by dst (CSR adjacency)
__device__ float  g_stats[STATS_LEN];    // zero-init; tail kernel re-zeroes

__device__ __forceinline__ float*  bufptr(int s)  { return s == 0 ? g_hA : g_hB; }
__device__ __forceinline__ __half* bufptrH(int s) { return s == 0 ? g_hHA : g_hHB; }

__device__ __forceinline__ void warpsum(float& v) {
#pragma unroll
    for (int o = 16; o; o >>= 1) v += __shfl_xor_sync(0xffffffffu, v, o);
}

// fp16 gather: 24 useful bytes in 2 loads (row is 32B aligned, single 128B line)
__device__ __forceinline__ void gathH(float* acc, const __half* hH, int s) {
    const __half* r = hH + ((size_t)s << 4);
    uint4 a = __ldg(reinterpret_cast<const uint4*>(r));
    uint2 b = __ldg(reinterpret_cast<const uint2*>(r + 8));
    float2 f;
    f = __half22float2(*reinterpret_cast<__half2*>(&a.x)); acc[0] += f.x; acc[1] += f.y;
    f = __half22float2(*reinterpret_cast<__half2*>(&a.y)); acc[2] += f.x; acc[3] += f.y;
    f = __half22float2(*reinterpret_cast<__half2*>(&a.z)); acc[4] += f.x; acc[5] += f.y;
    f = __half22float2(*reinterpret_cast<__half2*>(&a.w)); acc[6] += f.x; acc[7] += f.y;
    f = __half22float2(*reinterpret_cast<__half2*>(&b.x)); acc[8] += f.x; acc[9] += f.y;
    f = __half22float2(*reinterpret_cast<__half2*>(&b.y)); acc[10] += f.x; acc[11] += f.y;
}

__device__ __forceinline__ void storeH(__half* hH, int i, const float* out) {
    __half* r = hH + ((size_t)i << 4);
    uint4 a; uint2 b;
    *reinterpret_cast<__half2*>(&a.x) = __floats2half2_rn(out[0], out[1]);
    *reinterpret_cast<__half2*>(&a.y) = __floats2half2_rn(out[2], out[3]);
    *reinterpret_cast<__half2*>(&a.z) = __floats2half2_rn(out[4], out[5]);
    *reinterpret_cast<__half2*>(&a.w) = __floats2half2_rn(out[6], out[7]);
    *reinterpret_cast<__half2*>(&b.x) = __floats2half2_rn(out[8], out[9]);
    *reinterpret_cast<__half2*>(&b.y) = __floats2half2_rn(out[10], out[11]);
    *reinterpret_cast<uint4*>(r) = a;
    *reinterpret_cast<uint2*>(r + 8) = b;
}

// ---------------- CSR build ----------------

// degree histogram (g_deg pre-zeroed by load-time init / tail kernel) + x packing
__global__ void k_degx(const int* __restrict__ ei, const float* __restrict__ x) {
    int e = blockIdx.x * blockDim.x + threadIdx.x;
    if (e < N_EDGES) atomicAdd(&g_deg[ei[N_EDGES + e]], 1);
    if (e < N_NODES) {
        g_xp[e] = make_float4(x[3 * e], x[3 * e + 1], x[3 * e + 2], 0.f);
    }
}

// local exclusive scan: 1024 blocks x 1024 elements (256 thr x 4)
__global__ void k_scanA() {
    __shared__ int sh[256];
    int t = threadIdx.x;
    int base = blockIdx.x * 1024 + t * 4;
    int4 d = *reinterpret_cast<int4*>(&g_deg[base]);
    int s1 = d.x + d.y, s2 = s1 + d.z, tot = s2 + d.w;
    sh[t] = tot;
    __syncthreads();
#pragma unroll
    for (int o = 1; o < 256; o <<= 1) {
        int v = (t >= o) ? sh[t - o] : 0;
        __syncthreads();
        sh[t] += v;
        __syncthreads();
    }
    int excl = sh[t] - tot;
    g_off[base + 0] = excl;
    g_off[base + 1] = excl + d.x;
    g_off[base + 2] = excl + s1;
    g_off[base + 3] = excl + s2;
    if (t == 255) g_bsum[blockIdx.x] = sh[255];
}

// finalize: each block (256 nodes) adds the prefix of its 1024-chunk
__global__ void k_scanB() {
    __shared__ int sred[256];
    int t = threadIdx.x;
    int q = blockIdx.x >> 2;   // chunk index of this block's nodes
    // sum of g_bsum[j] for j < q
    int4 v = *reinterpret_cast<int4*>(&g_bsum[t * 4]);
    int j0 = t * 4;
    int s = (j0 + 0 < q ? v.x : 0) + (j0 + 1 < q ? v.y : 0)
          + (j0 + 2 < q ? v.z : 0) + (j0 + 3 < q ? v.w : 0);
    warpsum(*reinterpret_cast<float*>(&s));   // int bits via float shfl is wrong; do int reduce below
    // (redo properly with int shuffles)
    s = (j0 + 0 < q ? v.x : 0) + (j0 + 1 < q ? v.y : 0)
      + (j0 + 2 < q ? v.z : 0) + (j0 + 3 < q ? v.w : 0);
#pragma unroll
    for (int o = 16; o; o >>= 1) s += __shfl_xor_sync(0xffffffffu, s, o);
    if ((t & 31) == 0) sred[t >> 5] = s;
    __syncthreads();
    int S;
    {
        int r0 = (t < 8) ? sred[t] : 0;
        // reduce 8 warp partials (block has 256 thr = 8 warps)
        if (t < 8) {
#pragma unroll
            for (int o = 4; o; o >>= 1) r0 += __shfl_xor_sync(0xffu, r0, o);
        }
        if (t == 0) sred[0] = r0;
        __syncthreads();
        S = sred[0];
    }
    int i = blockIdx.x * 256 + t;
    int val = g_off[i] + S;
    g_off[i] = val;
    g_cur[i] = val;
    if (i == 0) g_off[N_NODES] = N_EDGES;
}

__global__ void k_place(const int* __restrict__ ei) {
    int e = blockIdx.x * blockDim.x + threadIdx.x;
    if (e >= N_EDGES) return;
    int s = ei[e];
    int d = ei[N_EDGES + e];
    int p = atomicAdd(&g_cur[d], 1);
    g_srt[p] = s;
}

// ---------------- layer 1: float4-packed x gather (1 LDG/neighbor) ----------------
__global__ void k_node1f(const float* __restrict__ Wl1, const float* __restrict__ Wr1,
                         const float* __restrict__ b1) {
    __shared__ float sWl[36], sWr[36], sb[12], sSum[24];
    int t = threadIdx.x;
    if (t < 36) { sWl[t] = Wl1[t]; sWr[t] = Wr1[t]; }
    if (t < 12) sb[t] = b1[t];
    if (t < 24) sSum[t] = 0.f;
    __syncthreads();
    int i = blockIdx.x * blockDim.x + t;
    int beg = g_off[i], end = g_off[i + 1];
    float a0 = 0.f, a1 = 0.f, a2 = 0.f;
    int p = beg;
    for (; p + 2 <= end; p += 2) {
        int s0 = __ldg(&g_srt[p]), s1 = __ldg(&g_srt[p + 1]);
        float4 u = __ldg(&g_xp[s0]);
        float4 w = __ldg(&g_xp[s1]);
        a0 += u.x + w.x; a1 += u.y + w.y; a2 += u.z + w.z;
    }
    if (p < end) {
        float4 u = __ldg(&g_xp[__ldg(&g_srt[p])]);
        a0 += u.x; a1 += u.y; a2 += u.z;
    }
    int dg = end - beg;
    float inv = dg > 0 ? 1.f / (float)dg : 0.f;
    float m0 = a0 * inv, m1 = a1 * inv, m2 = a2 * inv;
    float4 xs = g_xp[i];
    float out[12];
#pragma unroll
    for (int k = 0; k < 12; k++) {
        float v = sb[k] + m0 * sWl[3 * k] + m1 * sWl[3 * k + 1] + m2 * sWl[3 * k + 2]
                        + xs.x * sWr[3 * k] + xs.y * sWr[3 * k + 1] + xs.z * sWr[3 * k + 2];
        out[k] = fmaxf(v, 0.f);
    }
    float4* hp = reinterpret_cast<float4*>(g_hA + (size_t)i * 12);
    hp[0] = make_float4(out[0], out[1], out[2], out[3]);
    hp[1] = make_float4(out[4], out[5], out[6], out[7]);
    hp[2] = make_float4(out[8], out[9], out[10], out[11]);
    storeH(g_hHA, i, out);
#pragma unroll
    for (int k = 0; k < 12; k++) {
        float s = out[k], q = out[k] * out[k];
        warpsum(s); warpsum(q);
        if ((t & 31) == 0) { atomicAdd(&sSum[k], s); atomicAdd(&sSum[12 + k], q); }
    }
    __syncthreads();
    if (t < 24) atomicAdd(&g_stats[t], sSum[t]);
}

// ---------------- layers 2..8: fp16 gather (2 LDG/neighbor), fp32 everything else ----
template <int MODE>
__global__ void k_nodef(int in_sel, int out_sel,
                        const float* __restrict__ Wl, const float* __restrict__ Wr,
                        const float* __restrict__ bias,
                        const float* __restrict__ bng, const float* __restrict__ bnb,
                        int sin_off, int sout_off,
                        const float* __restrict__ linW, const float* __restrict__ linb) {
    const float*  h_in  = bufptr(in_sel);
    const __half* hH_in = bufptrH(in_sel);
    float*  h_out  = bufptr(out_sel);
    __half* hH_out = bufptrH(out_sel);
    __shared__ float sWl[144], sWr[144], sb[12], sa[12], sc[12], sSum[24], sLW[36], sLB[6];
    int t = threadIdx.x;
    if (t < 144) { sWl[t] = Wl[t]; sWr[t] = Wr[t]; }
    if (t < 12) {
        sb[t] = bias[t];
        float mean = g_stats[sin_off + t] * (1.f / N_NODES);
        float var  = g_stats[sin_off + 12 + t] * (1.f / N_NODES) - mean * mean;
        float a = bng[t] * rsqrtf(var + EPSV);
        sa[t] = a;
        sc[t] = bnb[t] - mean * a;
    }
    if (t < 24) sSum[t] = 0.f;
    if (MODE == 1) {
        if (t < 36) sLW[t] = linW[t];
        if (t < 6)  sLB[t] = linb[t];
    }
    __syncthreads();
    int i = blockIdx.x * blockDim.x + t;
    int beg = g_off[i], end = g_off[i + 1];
    float acc[12];
#pragma unroll
    for (int j = 0; j < 12; j++) acc[j] = 0.f;
    int p = beg;
    for (; p + 2 <= end; p += 2) {
        int s0 = __ldg(&g_srt[p]), s1 = __ldg(&g_srt[p + 1]);
        gathH(acc, hH_in, s0);
        gathH(acc, hH_in, s1);
    }
    if (p < end) gathH(acc, hH_in, __ldg(&g_srt[p]));

    const float4* hp = reinterpret_cast<const float4*>(h_in + (size_t)i * 12);
    float4 h0 = hp[0], h1 = hp[1], h2 = hp[2];
    float hv[12] = {h0.x, h0.y, h0.z, h0.w, h1.x, h1.y, h1.z, h1.w, h2.x, h2.y, h2.z, h2.w};
    int dg = end - beg;
    float gate = dg > 0 ? 1.f : 0.f;
    float inv  = dg > 0 ? 1.f / (float)dg : 0.f;
    float m[12], hb[12];
#pragma unroll
    for (int j = 0; j < 12; j++) {
        m[j]  = acc[j] * inv * sa[j] + sc[j] * gate;   // bn(mean) fold; isolated -> 0
        hb[j] = hv[j] * sa[j] + sc[j];
    }
    float out[12];
#pragma unroll
    for (int k = 0; k < 12; k++) {
        float v = sb[k];
#pragma unroll
        for (int j = 0; j < 12; j++) v += m[j] * sWl[12 * k + j] + hb[j] * sWr[12 * k + j];
        out[k] = fmaxf(v, 0.f);
    }
    float4* op = reinterpret_cast<float4*>(h_out + (size_t)i * 12);
    op[0] = make_float4(out[0], out[1], out[2], out[3]);
    op[1] = make_float4(out[4], out[5], out[6], out[7]);
    op[2] = make_float4(out[8], out[9], out[10], out[11]);
    storeH(hH_out, i, out);
    if (MODE == 0) {
#pragma unroll
        for (int k = 0; k < 12; k++) {
            float s = out[k], q = out[k] * out[k];
            warpsum(s); warpsum(q);
            if ((t & 31) == 0) { atomicAdd(&sSum[k], s); atomicAdd(&sSum[12 + k], q); }
        }
        __syncthreads();
        if (t < 24) atomicAdd(&g_stats[sout_off + t], sSum[t]);
    } else {
#pragma unroll
        for (int k = 0; k < 6; k++) {
            float za = sLB[k], zb = sLB[k];
#pragma unroll
            for (int j = 0; j < 6; j++) { za += out[j] * sLW[6 * k + j]; zb += out[6 + j] * sLW[6 * k + j]; }
            float s = za + zb, q = za * za + zb * zb;
            warpsum(s); warpsum(q);
            if ((t & 31) == 0) { atomicAdd(&sSum[k], s); atomicAdd(&sSum[6 + k], q); }
        }
        __syncthreads();
        if (t < 12) atomicAdd(&g_stats[sout_off + t], sSum[t]);
    }
}

// ---------------- head (all fp32) ----------------
template <int PASS>
__global__ void k_head(int in_sel, int out_sel,
                       const float* __restrict__ linW, const float* __restrict__ linb,
                       const float* __restrict__ g6, const float* __restrict__ b6,
                       int sin_off, int sout_off,
                       const float* __restrict__ oW, const float* __restrict__ ob,
                       float* __restrict__ outp) {
    const float* h_in = bufptr(in_sel);
    float* h_out = bufptr(out_sel);
    __shared__ float sLW[36], sLB[6], sa[6], sc[6], sSum[12], sOW[7];
    int t = threadIdx.x;
    if (t < 36) sLW[t] = linW[t];
    if (t < 6) {
        sLB[t] = linb[t];
        const float invM = 1.f / (2.f * N_NODES);
        float mean = g_stats[sin_off + t] * invM;
        float var  = g_stats[sin_off + 6 + t] * invM - mean * mean;
        float a = g6[t] * rsqrtf(var + EPSV);
        sa[t] = a;
        sc[t] = b6[t] - mean * a;
    }
    if (t < 12) sSum[t] = 0.f;
    if (PASS == 3) { if (t < 6) sOW[t] = oW[t]; if (t == 6) sOW[6] = ob[0]; }
    __syncthreads();
    int i = blockIdx.x * blockDim.x + t;
    const float4* hp = reinterpret_cast<const float4*>(h_in + (size_t)i * 12);
    float4 h0 = hp[0], h1 = hp[1], h2 = hp[2];
    float hv[12] = {h0.x, h0.y, h0.z, h0.w, h1.x, h1.y, h1.z, h1.w, h2.x, h2.y, h2.z, h2.w};
    float r[12];
#pragma unroll
    for (int half = 0; half < 2; half++) {
#pragma unroll
        for (int k = 0; k < 6; k++) {
            float z = sLB[k];
#pragma unroll
            for (int j = 0; j < 6; j++) z += hv[6 * half + j] * sLW[6 * k + j];
            r[6 * half + k] = fmaxf(z * sa[k] + sc[k], 0.f);
        }
    }
    if (PASS < 3) {
        float4* op = reinterpret_cast<float4*>(h_out + (size_t)i * 12);
        op[0] = make_float4(r[0], r[1], r[2], r[3]);
        op[1] = make_float4(r[4], r[5], r[6], r[7]);
        op[2] = make_float4(r[8], r[9], r[10], r[11]);
#pragma unroll
        for (int k = 0; k < 6; k++) {
            float za = sLB[k], zb = sLB[k];
#pragma unroll
            for (int j = 0; j < 6; j++) { za += r[j] * sLW[6 * k + j]; zb += r[6 + j] * sLW[6 * k + j]; }
            float s = za + zb, q = za * za + zb * zb;
            warpsum(s); warpsum(q);
            if ((t & 31) == 0) { atomicAdd(&sSum[k], s); atomicAdd(&sSum[6 + k], q); }
        }
        __syncthreads();
        if (t < 12) atomicAdd(&g_stats[sout_off + t], sSum[t]);
    } else {
        float oa = sOW[6], obv = sOW[6];
#pragma unroll
        for (int j = 0; j < 6; j++) { oa += r[j] * sOW[j]; obv += r[6 + j] * sOW[j]; }
        outp[2 * i]     = 1.f / (1.f + expf(-oa));
        outp[2 * i + 1] = 1.f / (1.f + expf(-obv));
    }
}

// tail: restore zeroed state for the next call (first call uses load-time zero-init)
__global__ void k_tail() {
    int i = blockIdx.x * blockDim.x + threadIdx.x;
    int stride = gridDim.x * blockDim.x;
    int4 z4 = make_int4(0, 0, 0, 0);
    int4* d4 = reinterpret_cast<int4*>(g_deg);
    for (int j = i; j < N_NODES / 4; j += stride) d4[j] = z4;
    if (i < STATS_LEN) g_stats[i] = 0.f;
}

// ---------------- launch ----------------
extern "C" void kernel_launch(void* const* d_in, const int* in_sizes, int n_in,
                              void* d_out, int out_size) {
    const float* x    = (const float*)d_in[0];
    const int*   ei   = (const int*)d_in[1];
    const float* Wl1  = (const float*)d_in[2];
    const float* Wr1  = (const float*)d_in[3];
    const float* b1   = (const float*)d_in[4];
    const float* Wl   = (const float*)d_in[5];
    const float* Wr   = (const float*)d_in[6];
    const float* bb   = (const float*)d_in[7];
    const float* bng  = (const float*)d_in[8];
    const float* bnb  = (const float*)d_in[9];
    const float* linW = (const float*)d_in[10];
    const float* linb = (const float*)d_in[11];
    const float* g6   = (const float*)d_in[12];
    const float* b6   = (const float*)d_in[13];
    const float* oW   = (const float*)d_in[14];
    const float* ob   = (const float*)d_in[15];
    float* outp = (float*)d_out;

    const int EB = N_EDGES / 256;   // 16384
    const int NB = N_NODES / 256;   // 4096

    // CSR build (g_deg/g_stats are zero at entry: load-time init or k_tail)
    k_degx<<<EB, 256>>>(ei, x);
    k_scanA<<<1024, 256>>>();
    k_scanB<<<NB, 256>>>();
    k_place<<<EB, 256>>>(ei);

    // conv1 -> hA + fp16 mirror, stats slot 0
    k_node1f<<<NB, 256>>>(Wl1, Wr1, b1);

    int in_sel = 0, out_sel = 1;
    for (int i = 0; i < 7; i++) {
        int sin_off = 24 * i;
        if (i < 6) {
            k_nodef<0><<<NB, 256>>>(in_sel, out_sel, Wl + 144 * i, Wr + 144 * i, bb + 12 * i,
                                    bng + 12 * i, bnb + 12 * i, sin_off, 24 * (i + 1),
                                    linW, linb);
        } else {
            k_nodef<1><<<NB, 256>>>(in_sel, out_sel, Wl + 144 * i, Wr + 144 * i, bb + 12 * i,
                                    bng + 12 * i, bnb + 12 * i, sin_off, 7 * 24,
                                    linW, linb);
        }
        int tmp = in_sel; in_sel = out_sel; out_sel = tmp;
    }
    // conv8 output in hB (in_sel==1). Head: hB -> hA -> hB -> out.
    k_head<1><<<NB, 256>>>(1, 0, linW, linb, g6, b6, 168, 180, oW, ob, outp);
    k_head<2><<<NB, 256>>>(0, 1, linW, linb, g6, b6, 180, 192, oW, ob, outp);
    k_head<3><<<NB, 256>>>(1, 0, linW, linb, g6, b6, 192, 0, oW, ob, outp);

    // restore zeroed state for next call
    k_tail<<<1024, 256>>>();
}